// round 11
// baseline (speedup 1.0000x reference)
#include <cuda_runtime.h>
#include <cuda_fp16.h>
#include <cstdint>

// Problem dims: B=4,S=2048 -> M=8192; IC=K=4096; OC=N=4096; G=32 (group size 128)
#define MT 8192
#define NT 4096
#define KTOT 4096
#define GT 32

// ---------------- scratch (device globals: allocation-free) ----------------
__device__ __align__(16) __half g_qx[(size_t)MT * KTOT];   // quantized activations (exact ints, fp16)
__device__ __align__(16) __half g_wh[(size_t)NT * KTOT];   // dequantized weights fp16
__device__ float g_xs[MT];                                  // per-token scale

// ---------------- fused prep: blocks [0,MT) = token quant, rest = weight dequant ----------------
__global__ void prep_kernel(const float* __restrict__ x, const int* __restrict__ qw,
                            const int* __restrict__ zr, const int* __restrict__ qs,
                            const float* __restrict__ bs, const float* __restrict__ ss) {
    const int tid = threadIdx.x;  // 256 threads
    if (blockIdx.x < MT) {
        const int row = blockIdx.x;
        const float4* xr = reinterpret_cast<const float4*>(x + (size_t)row * KTOT);
        float4 v[4];
        float amax = 0.f;
#pragma unroll
        for (int i = 0; i < 4; i++) {
            v[i] = xr[tid + i * 256];
            amax = fmaxf(amax, fmaxf(fmaxf(fabsf(v[i].x), fabsf(v[i].y)),
                                     fmaxf(fabsf(v[i].z), fabsf(v[i].w))));
        }
#pragma unroll
        for (int o = 16; o > 0; o >>= 1)
            amax = fmaxf(amax, __shfl_xor_sync(0xffffffffu, amax, o));
        __shared__ float red[8];
        if ((tid & 31) == 0) red[tid >> 5] = amax;
        __syncthreads();
        if (tid < 32) {
            float m = (tid < 8) ? red[tid] : 0.f;
#pragma unroll
            for (int o = 4; o > 0; o >>= 1)
                m = fmaxf(m, __shfl_xor_sync(0xffffffffu, m, o));
            if (tid == 0) red[0] = m;
        }
        __syncthreads();
        amax = red[0];
        const float s = amax / 127.0f;
        if (tid == 0) g_xs[row] = s;
        const float inv = 1.0f / fmaxf(s, 1e-8f);
        __half* qr = g_qx + (size_t)row * KTOT;
#pragma unroll
        for (int i = 0; i < 4; i++) {
            float q0 = fminf(fmaxf(rintf(v[i].x * inv), -127.f), 127.f);
            float q1 = fminf(fmaxf(rintf(v[i].y * inv), -127.f), 127.f);
            float q2 = fminf(fmaxf(rintf(v[i].z * inv), -127.f), 127.f);
            float q3 = fminf(fmaxf(rintf(v[i].w * inv), -127.f), 127.f);
            __half2 h01 = __floats2half2_rn(q0, q1);
            __half2 h23 = __floats2half2_rn(q2, q3);
            uint2 u;
            u.x = *reinterpret_cast<const unsigned*>(&h01);
            u.y = *reinterpret_cast<const unsigned*>(&h23);
            reinterpret_cast<uint2*>(qr)[tid + i * 256] = u;
        }
    } else {
        const size_t t = (size_t)(blockIdx.x - MT) * 256 + tid;
        const int o = (int)(t >> 9);
        const int chunk = (int)(t & 511);
        const int ic0 = chunk << 3;
        const int g = ic0 >> 7;
        const float z = (float)zr[o * GT + g];
        const float s = bs[o] + ss[o] * (float)qs[o * GT + g];
        const int4* qp = reinterpret_cast<const int4*>(qw + (size_t)o * KTOT + ic0);
        int4 q0 = qp[0], q1 = qp[1];
        __half2 h0 = __floats2half2_rn(((float)q0.x - z) * s, ((float)q0.y - z) * s);
        __half2 h1 = __floats2half2_rn(((float)q0.z - z) * s, ((float)q0.w - z) * s);
        __half2 h2 = __floats2half2_rn(((float)q1.x - z) * s, ((float)q1.y - z) * s);
        __half2 h3 = __floats2half2_rn(((float)q1.z - z) * s, ((float)q1.w - z) * s);
        uint4 u;
        u.x = *reinterpret_cast<const unsigned*>(&h0);
        u.y = *reinterpret_cast<const unsigned*>(&h1);
        u.z = *reinterpret_cast<const unsigned*>(&h2);
        u.w = *reinterpret_cast<const unsigned*>(&h3);
        *reinterpret_cast<uint4*>(g_wh + (size_t)o * KTOT + ic0) = u;
    }
}

// ---------------- GEMM: persistent CTAs, BM=128 BN=128 BK=64, 4 warps 64x64, 2 CTAs/SM ----------------
constexpr int BM = 128, BN = 128, BK = 64, STAGES = 3;
constexpr int ABYTES = BM * BK * 2;               // 16 KB  (128 rows x 128B, XOR-swizzled)
constexpr int BBYTES = BN * BK * 2;               // 16 KB
constexpr int STAGE_BYTES = ABYTES + BBYTES;      // 32 KB
constexpr int GSMEM = STAGES * STAGE_BYTES;       // 96 KB -> 2 CTAs/SM
constexpr int NX = NT / BN;                       // 32 tiles in n (power of 2)
constexpr int NTILES = NX * (MT / BM);            // 2048
constexpr int GRIDP = 296;                        // 2 CTAs x 148 SMs, one wave
constexpr int NIT = KTOT / BK;                    // 64 k-tiles per output tile

__device__ __forceinline__ uint32_t smem_u32(const void* p) {
    return (uint32_t)__cvta_generic_to_shared(p);
}

__device__ __forceinline__ void mma16816(float* c, const uint32_t* a, uint32_t b0, uint32_t b1) {
    asm volatile(
        "mma.sync.aligned.m16n8k16.row.col.f32.f16.f16.f32 "
        "{%0,%1,%2,%3}, {%4,%5,%6,%7}, {%8,%9}, {%0,%1,%2,%3};"
        : "+f"(c[0]), "+f"(c[1]), "+f"(c[2]), "+f"(c[3])
        : "r"(a[0]), "r"(a[1]), "r"(a[2]), "r"(a[3]), "r"(b0), "r"(b1));
}

__global__ void __launch_bounds__(128, 2) gemm_f16(float* __restrict__ out) {
    extern __shared__ __align__(1024) char smem[];
    const uint32_t tile0 = smem_u32(smem);

    const int tid = threadIdx.x;
    const int lane = tid & 31;
    const int wid = tid >> 5;               // 4 warps
    const int wm = (wid & 1) * 64;          // 2 x 64 = BM
    const int wn = (wid >> 1) * 64;         // 2 x 64 = BN

    // ---- load cursor: runs 2 k-tiles ahead of compute, across tile boundaries ----
    int lt = blockIdx.x;                    // tile being loaded
    int lkt = 0;                            // k-tile within lt
    const __half* lAg = g_qx + (size_t)((lt >> 5) * BM) * KTOT;
    const __half* lBg = g_wh + (size_t)((lt & (NX - 1)) * BN) * KTOT;

    auto load_stage = [&](int s) {
        if (lt < NTILES) {
            const int kk = lkt * BK;
            const uint32_t base = tile0 + s * STAGE_BYTES;
#pragma unroll
            for (int j = 0; j < 16; j++) {
                const int id = tid + j * 128;          // 0..1023 A chunks, 1024..2047 B
                const int isB = id >> 10;
                const int rid = id & 1023;
                const int r = rid >> 3;
                const int c = rid & 7;
                const uint32_t dst = base + isB * ABYTES + r * 128 + (((c ^ r) & 7) << 4);
                const __half* src = (isB ? lBg : lAg) + (size_t)r * KTOT + kk + c * 8;
                asm volatile("cp.async.cg.shared.global [%0], [%1], 16;" ::"r"(dst), "l"(src));
            }
        }
        asm volatile("cp.async.commit_group;" ::: "memory");
        if (++lkt == NIT) {
            lkt = 0;
            lt += GRIDP;
            if (lt < NTILES) {
                lAg = g_qx + (size_t)((lt >> 5) * BM) * KTOT;
                lBg = g_wh + (size_t)((lt & (NX - 1)) * BN) * KTOT;
            }
        }
    };

    float acc[4][8][4];

    // prologue: fill 2 stages
    load_stage(0);
    load_stage(1);
    asm volatile("cp.async.wait_group 1;" ::: "memory");
    __syncthreads();

    int p = 0;  // global pipeline position: compute stage = p % 3
    for (int t = blockIdx.x; t < NTILES; t += GRIDP) {
        const int n0 = (t & (NX - 1)) * BN;
        const int m0 = (t >> 5) * BM;

#pragma unroll
        for (int a = 0; a < 4; a++)
#pragma unroll
            for (int b = 0; b < 8; b++)
#pragma unroll
                for (int c = 0; c < 4; c++) acc[a][b][c] = 0.f;

        for (int kt = 0; kt < NIT; kt++, p++) {
            // issue loads 2 positions ahead
            load_stage((p + 2) % STAGES);

            const uint32_t Ab = tile0 + (p % STAGES) * STAGE_BYTES;
            const uint32_t Bb = Ab + ABYTES;

#pragma unroll
            for (int ks = 0; ks < 4; ks++) {  // 4 x k16
                uint32_t a[4][4];
#pragma unroll
                for (int mi = 0; mi < 4; mi++) {
                    const int row = wm + mi * 16 + (lane & 15);
                    const int chunk = ks * 2 + (lane >> 4);
                    const uint32_t addr = Ab + row * 128 + (((chunk ^ row) & 7) << 4);
                    asm volatile(
                        "ldmatrix.sync.aligned.m8n8.x4.shared.b16 {%0,%1,%2,%3}, [%4];"
                        : "=r"(a[mi][0]), "=r"(a[mi][1]), "=r"(a[mi][2]), "=r"(a[mi][3])
                        : "r"(addr));
                }
                uint32_t b[4][4];
#pragma unroll
                for (int nb = 0; nb < 4; nb++) {
                    const int grp = lane >> 3;
                    const int row = wn + nb * 16 + (grp >> 1) * 8 + (lane & 7);
                    const int chunk = ks * 2 + (grp & 1);
                    const uint32_t addr = Bb + row * 128 + (((chunk ^ row) & 7) << 4);
                    asm volatile(
                        "ldmatrix.sync.aligned.m8n8.x4.shared.b16 {%0,%1,%2,%3}, [%4];"
                        : "=r"(b[nb][0]), "=r"(b[nb][1]), "=r"(b[nb][2]), "=r"(b[nb][3])
                        : "r"(addr));
                }
#pragma unroll
                for (int mi = 0; mi < 4; mi++)
#pragma unroll
                    for (int ni = 0; ni < 8; ni++)
                        mma16816(acc[mi][ni], a[mi], b[ni >> 1][(ni & 1) * 2],
                                 b[ni >> 1][(ni & 1) * 2 + 1]);
            }

            if (kt == NIT - 1) {
                // epilogue (reg->gmem only) overlaps the load wait for the next tile
#pragma unroll
                for (int mi = 0; mi < 4; mi++) {
                    const int r0 = m0 + wm + mi * 16 + (lane >> 2);
                    const float s0 = g_xs[r0];
                    const float s1 = g_xs[r0 + 8];
#pragma unroll
                    for (int ni = 0; ni < 8; ni++) {
                        const int cc = n0 + wn + ni * 8 + (lane & 3) * 2;
                        float2 v0 = make_float2(acc[mi][ni][0] * s0, acc[mi][ni][1] * s0);
                        float2 v1 = make_float2(acc[mi][ni][2] * s1, acc[mi][ni][3] * s1);
                        *reinterpret_cast<float2*>(out + (size_t)r0 * NT + cc) = v0;
                        *reinterpret_cast<float2*>(out + (size_t)(r0 + 8) * NT + cc) = v1;
                    }
                }
            }

            asm volatile("cp.async.wait_group 1;" ::: "memory");
            __syncthreads();
        }
    }
}

// ---------------- launch ----------------
extern "C" void kernel_launch(void* const* d_in, const int* in_sizes, int n_in,
                              void* d_out, int out_size) {
    const float* x = (const float*)d_in[0];
    const int* qw = (const int*)d_in[1];
    const int* zr = (const int*)d_in[2];
    const int* qs = (const int*)d_in[3];
    const float* bs = (const float*)d_in[4];
    const float* ss = (const float*)d_in[5];
    float* out = (float*)d_out;

    cudaFuncSetAttribute(gemm_f16, cudaFuncAttributeMaxDynamicSharedMemorySize, GSMEM);

    prep_kernel<<<MT + (NT * 512) / 256, 256>>>(x, qw, zr, qs, bs, ss);
    gemm_f16<<<GRIDP, 128, GSMEM>>>(out);
}

// round 12
// speedup vs baseline: 1.1890x; 1.1890x over previous
#include <cuda_runtime.h>
#include <cuda_fp16.h>
#include <cstdint>

// Problem dims: B=4,S=2048 -> M=8192; IC=K=4096; OC=N=4096; G=32 (group size 128)
#define MT 8192
#define NT 4096
#define KTOT 4096
#define GT 32

// ---------------- scratch (device globals: allocation-free) ----------------
__device__ __align__(16) __half g_qx[(size_t)MT * KTOT];   // quantized activations (exact ints, fp16)
__device__ __align__(16) __half g_wh[(size_t)NT * KTOT];   // dequantized weights fp16
__device__ float g_xs[MT];                                  // per-token scale

// ---------------- fused prep: blocks [0,MT) = token quant, rest = weight dequant ----------------
__global__ void prep_kernel(const float* __restrict__ x, const int* __restrict__ qw,
                            const int* __restrict__ zr, const int* __restrict__ qs,
                            const float* __restrict__ bs, const float* __restrict__ ss) {
    const int tid = threadIdx.x;  // 256 threads
    if (blockIdx.x < MT) {
        const int row = blockIdx.x;
        const float4* xr = reinterpret_cast<const float4*>(x + (size_t)row * KTOT);
        float4 v[4];
        float amax = 0.f;
#pragma unroll
        for (int i = 0; i < 4; i++) {
            v[i] = xr[tid + i * 256];
            amax = fmaxf(amax, fmaxf(fmaxf(fabsf(v[i].x), fabsf(v[i].y)),
                                     fmaxf(fabsf(v[i].z), fabsf(v[i].w))));
        }
#pragma unroll
        for (int o = 16; o > 0; o >>= 1)
            amax = fmaxf(amax, __shfl_xor_sync(0xffffffffu, amax, o));
        __shared__ float red[8];
        if ((tid & 31) == 0) red[tid >> 5] = amax;
        __syncthreads();
        if (tid < 32) {
            float m = (tid < 8) ? red[tid] : 0.f;
#pragma unroll
            for (int o = 4; o > 0; o >>= 1)
                m = fmaxf(m, __shfl_xor_sync(0xffffffffu, m, o));
            if (tid == 0) red[0] = m;
        }
        __syncthreads();
        amax = red[0];
        const float s = amax / 127.0f;
        if (tid == 0) g_xs[row] = s;
        const float inv = 1.0f / fmaxf(s, 1e-8f);
        __half* qr = g_qx + (size_t)row * KTOT;
#pragma unroll
        for (int i = 0; i < 4; i++) {
            float q0 = fminf(fmaxf(rintf(v[i].x * inv), -127.f), 127.f);
            float q1 = fminf(fmaxf(rintf(v[i].y * inv), -127.f), 127.f);
            float q2 = fminf(fmaxf(rintf(v[i].z * inv), -127.f), 127.f);
            float q3 = fminf(fmaxf(rintf(v[i].w * inv), -127.f), 127.f);
            __half2 h01 = __floats2half2_rn(q0, q1);
            __half2 h23 = __floats2half2_rn(q2, q3);
            uint2 u;
            u.x = *reinterpret_cast<const unsigned*>(&h01);
            u.y = *reinterpret_cast<const unsigned*>(&h23);
            reinterpret_cast<uint2*>(qr)[tid + i * 256] = u;
        }
    } else {
        const size_t t = (size_t)(blockIdx.x - MT) * 256 + tid;
        const int o = (int)(t >> 9);
        const int chunk = (int)(t & 511);
        const int ic0 = chunk << 3;
        const int g = ic0 >> 7;
        const float z = (float)zr[o * GT + g];
        const float s = bs[o] + ss[o] * (float)qs[o * GT + g];
        const int4* qp = reinterpret_cast<const int4*>(qw + (size_t)o * KTOT + ic0);
        int4 q0 = qp[0], q1 = qp[1];
        __half2 h0 = __floats2half2_rn(((float)q0.x - z) * s, ((float)q0.y - z) * s);
        __half2 h1 = __floats2half2_rn(((float)q0.z - z) * s, ((float)q0.w - z) * s);
        __half2 h2 = __floats2half2_rn(((float)q1.x - z) * s, ((float)q1.y - z) * s);
        __half2 h3 = __floats2half2_rn(((float)q1.z - z) * s, ((float)q1.w - z) * s);
        uint4 u;
        u.x = *reinterpret_cast<const unsigned*>(&h0);
        u.y = *reinterpret_cast<const unsigned*>(&h1);
        u.z = *reinterpret_cast<const unsigned*>(&h2);
        u.w = *reinterpret_cast<const unsigned*>(&h3);
        *reinterpret_cast<uint4*>(g_wh + (size_t)o * KTOT + ic0) = u;
    }
}

// ---------------- GEMM: BM=128 BN=128 BK=64, 4 warps 64x64, 2 CTAs/SM (R10 + reorder) ----------------
constexpr int BM = 128, BN = 128, BK = 64, STAGES = 3;
constexpr int ABYTES = BM * BK * 2;               // 16 KB  (128 rows x 128B, XOR-swizzled)
constexpr int BBYTES = BN * BK * 2;               // 16 KB
constexpr int STAGE_BYTES = ABYTES + BBYTES;      // 32 KB
constexpr int GSMEM = STAGES * STAGE_BYTES;       // 96 KB -> 2 CTAs/SM

__device__ __forceinline__ uint32_t smem_u32(const void* p) {
    return (uint32_t)__cvta_generic_to_shared(p);
}

__device__ __forceinline__ void mma16816(float* c, const uint32_t* a, uint32_t b0, uint32_t b1) {
    asm volatile(
        "mma.sync.aligned.m16n8k16.row.col.f32.f16.f16.f32 "
        "{%0,%1,%2,%3}, {%4,%5,%6,%7}, {%8,%9}, {%0,%1,%2,%3};"
        : "+f"(c[0]), "+f"(c[1]), "+f"(c[2]), "+f"(c[3])
        : "r"(a[0]), "r"(a[1]), "r"(a[2]), "r"(a[3]), "r"(b0), "r"(b1));
}

__global__ void __launch_bounds__(128, 2) gemm_f16(float* __restrict__ out) {
    extern __shared__ __align__(1024) char smem[];
    const uint32_t tile0 = smem_u32(smem);

    const int tid = threadIdx.x;
    const int lane = tid & 31;
    const int wid = tid >> 5;               // 4 warps
    const int wm = (wid & 1) * 64;          // 2 x 64 = BM
    const int wn = (wid >> 1) * 64;         // 2 x 64 = BN
    const int n0 = blockIdx.x * BN;
    const int m0 = blockIdx.y * BM;

    const __half* Ag = g_qx + (size_t)m0 * KTOT;
    const __half* Bg = g_wh + (size_t)n0 * KTOT;

    // rows stored as 128B (64 halves), 8 x 16B chunks, chunk XOR-swizzled by (row & 7)
    auto load_stage = [&](int s, int kk) {
        const uint32_t base = tile0 + s * STAGE_BYTES;
#pragma unroll
        for (int j = 0; j < 16; j++) {
            const int id = tid + j * 128;          // 0..1023 A chunks, 1024..2047 B
            const int isB = id >> 10;
            const int rid = id & 1023;
            const int r = rid >> 3;
            const int c = rid & 7;
            const uint32_t dst = base + isB * ABYTES + r * 128 + (((c ^ r) & 7) << 4);
            const __half* src = (isB ? Bg : Ag) + (size_t)r * KTOT + kk + c * 8;
            asm volatile("cp.async.cg.shared.global [%0], [%1], 16;" ::"r"(dst), "l"(src));
        }
        asm volatile("cp.async.commit_group;" ::: "memory");
    };

    float acc[4][8][4];
#pragma unroll
    for (int a = 0; a < 4; a++)
#pragma unroll
        for (int b = 0; b < 8; b++)
#pragma unroll
            for (int c = 0; c < 4; c++) acc[a][b][c] = 0.f;

    // one ks-step (ldmatrix + 32 mma) of the current stage
    auto ks_step = [&](uint32_t Ab, uint32_t Bb, int ks) {
        uint32_t a[4][4];
#pragma unroll
        for (int mi = 0; mi < 4; mi++) {
            const int row = wm + mi * 16 + (lane & 15);
            const int chunk = ks * 2 + (lane >> 4);
            const uint32_t addr = Ab + row * 128 + (((chunk ^ row) & 7) << 4);
            asm volatile(
                "ldmatrix.sync.aligned.m8n8.x4.shared.b16 {%0,%1,%2,%3}, [%4];"
                : "=r"(a[mi][0]), "=r"(a[mi][1]), "=r"(a[mi][2]), "=r"(a[mi][3])
                : "r"(addr));
        }
        uint32_t b[4][4];
#pragma unroll
        for (int nb = 0; nb < 4; nb++) {
            const int grp = lane >> 3;
            const int row = wn + nb * 16 + (grp >> 1) * 8 + (lane & 7);
            const int chunk = ks * 2 + (grp & 1);
            const uint32_t addr = Bb + row * 128 + (((chunk ^ row) & 7) << 4);
            asm volatile(
                "ldmatrix.sync.aligned.m8n8.x4.shared.b16 {%0,%1,%2,%3}, [%4];"
                : "=r"(b[nb][0]), "=r"(b[nb][1]), "=r"(b[nb][2]), "=r"(b[nb][3])
                : "r"(addr));
        }
#pragma unroll
        for (int mi = 0; mi < 4; mi++)
#pragma unroll
            for (int ni = 0; ni < 8; ni++)
                mma16816(acc[mi][ni], a[mi], b[ni >> 1][(ni & 1) * 2],
                         b[ni >> 1][(ni & 1) * 2 + 1]);
    };

    const int NIT = KTOT / BK;  // 64
    load_stage(0, 0);
    load_stage(1, BK);
    asm volatile("cp.async.wait_group 1;" ::: "memory");
    __syncthreads();

    for (int kt = 0; kt < NIT; kt++) {
        const int s = kt % STAGES;
        const uint32_t Ab = tile0 + s * STAGE_BYTES;
        const uint32_t Bb = Ab + ABYTES;

        // post-barrier: start tensor work immediately (ks=0), THEN issue next loads
        ks_step(Ab, Bb, 0);

        if (kt + 2 < NIT) {
            load_stage((kt + 2) % STAGES, (kt + 2) * BK);
        } else {
            asm volatile("cp.async.commit_group;" ::: "memory");
        }

#pragma unroll
        for (int ks = 1; ks < 4; ks++) ks_step(Ab, Bb, ks);

        asm volatile("cp.async.wait_group 1;" ::: "memory");
        __syncthreads();
    }

    // epilogue: scale by per-token x_scale, write fp32
#pragma unroll
    for (int mi = 0; mi < 4; mi++) {
        const int r0 = m0 + wm + mi * 16 + (lane >> 2);
        const float s0 = g_xs[r0];
        const float s1 = g_xs[r0 + 8];
#pragma unroll
        for (int ni = 0; ni < 8; ni++) {
            const int cc = n0 + wn + ni * 8 + (lane & 3) * 2;
            float2 v0 = make_float2(acc[mi][ni][0] * s0, acc[mi][ni][1] * s0);
            float2 v1 = make_float2(acc[mi][ni][2] * s1, acc[mi][ni][3] * s1);
            *reinterpret_cast<float2*>(out + (size_t)r0 * NT + cc) = v0;
            *reinterpret_cast<float2*>(out + (size_t)(r0 + 8) * NT + cc) = v1;
        }
    }
}

// ---------------- launch ----------------
extern "C" void kernel_launch(void* const* d_in, const int* in_sizes, int n_in,
                              void* d_out, int out_size) {
    const float* x = (const float*)d_in[0];
    const int* qw = (const int*)d_in[1];
    const int* zr = (const int*)d_in[2];
    const int* qs = (const int*)d_in[3];
    const float* bs = (const float*)d_in[4];
    const float* ss = (const float*)d_in[5];
    float* out = (float*)d_out;

    cudaFuncSetAttribute(gemm_f16, cudaFuncAttributeMaxDynamicSharedMemorySize, GSMEM);

    prep_kernel<<<MT + (NT * 512) / 256, 256>>>(x, qw, zr, qs, bs, ss);
    gemm_f16<<<dim3(NT / BN, MT / BM), 128, GSMEM>>>(out);
}

// round 13
// speedup vs baseline: 1.2259x; 1.0310x over previous
#include <cuda_runtime.h>
#include <cuda_fp16.h>
#include <cstdint>

// Problem dims: B=4,S=2048 -> M=8192; IC=K=4096; OC=N=4096; G=32 (group size 128)
#define MT 8192
#define NT 4096
#define KTOT 4096
#define GT 32

// ---------------- scratch (device globals: allocation-free) ----------------
__device__ __align__(16) __half g_qx[(size_t)MT * KTOT];   // quantized activations (exact ints, fp16)
__device__ __align__(16) __half g_wh[(size_t)NT * KTOT];   // dequantized weights fp16
__device__ float g_xs[MT];                                  // per-token scale

// ---------------- fused prep: blocks [0,MT) = token quant, rest = weight dequant ----------------
__global__ void prep_kernel(const float* __restrict__ x, const int* __restrict__ qw,
                            const int* __restrict__ zr, const int* __restrict__ qs,
                            const float* __restrict__ bs, const float* __restrict__ ss) {
    const int tid = threadIdx.x;  // 256 threads
    if (blockIdx.x < MT) {
        const int row = blockIdx.x;
        const float4* xr = reinterpret_cast<const float4*>(x + (size_t)row * KTOT);
        float4 v[4];
        float amax = 0.f;
#pragma unroll
        for (int i = 0; i < 4; i++) {
            v[i] = xr[tid + i * 256];
            amax = fmaxf(amax, fmaxf(fmaxf(fabsf(v[i].x), fabsf(v[i].y)),
                                     fmaxf(fabsf(v[i].z), fabsf(v[i].w))));
        }
#pragma unroll
        for (int o = 16; o > 0; o >>= 1)
            amax = fmaxf(amax, __shfl_xor_sync(0xffffffffu, amax, o));
        __shared__ float red[8];
        if ((tid & 31) == 0) red[tid >> 5] = amax;
        __syncthreads();
        if (tid < 32) {
            float m = (tid < 8) ? red[tid] : 0.f;
#pragma unroll
            for (int o = 4; o > 0; o >>= 1)
                m = fmaxf(m, __shfl_xor_sync(0xffffffffu, m, o));
            if (tid == 0) red[0] = m;
        }
        __syncthreads();
        amax = red[0];
        const float s = amax / 127.0f;
        if (tid == 0) g_xs[row] = s;
        const float inv = 1.0f / fmaxf(s, 1e-8f);
        __half* qr = g_qx + (size_t)row * KTOT;
#pragma unroll
        for (int i = 0; i < 4; i++) {
            float q0 = fminf(fmaxf(rintf(v[i].x * inv), -127.f), 127.f);
            float q1 = fminf(fmaxf(rintf(v[i].y * inv), -127.f), 127.f);
            float q2 = fminf(fmaxf(rintf(v[i].z * inv), -127.f), 127.f);
            float q3 = fminf(fmaxf(rintf(v[i].w * inv), -127.f), 127.f);
            __half2 h01 = __floats2half2_rn(q0, q1);
            __half2 h23 = __floats2half2_rn(q2, q3);
            uint2 u;
            u.x = *reinterpret_cast<const unsigned*>(&h01);
            u.y = *reinterpret_cast<const unsigned*>(&h23);
            reinterpret_cast<uint2*>(qr)[tid + i * 256] = u;
        }
    } else {
        const size_t t = (size_t)(blockIdx.x - MT) * 256 + tid;
        const int o = (int)(t >> 9);
        const int chunk = (int)(t & 511);
        const int ic0 = chunk << 3;
        const int g = ic0 >> 7;
        const float z = (float)zr[o * GT + g];
        const float s = bs[o] + ss[o] * (float)qs[o * GT + g];
        const int4* qp = reinterpret_cast<const int4*>(qw + (size_t)o * KTOT + ic0);
        int4 q0 = qp[0], q1 = qp[1];
        __half2 h0 = __floats2half2_rn(((float)q0.x - z) * s, ((float)q0.y - z) * s);
        __half2 h1 = __floats2half2_rn(((float)q0.z - z) * s, ((float)q0.w - z) * s);
        __half2 h2 = __floats2half2_rn(((float)q1.x - z) * s, ((float)q1.y - z) * s);
        __half2 h3 = __floats2half2_rn(((float)q1.z - z) * s, ((float)q1.w - z) * s);
        uint4 u;
        u.x = *reinterpret_cast<const unsigned*>(&h0);
        u.y = *reinterpret_cast<const unsigned*>(&h1);
        u.z = *reinterpret_cast<const unsigned*>(&h2);
        u.w = *reinterpret_cast<const unsigned*>(&h3);
        *reinterpret_cast<uint4*>(g_wh + (size_t)o * KTOT + ic0) = u;
    }
}

// ---------------- GEMM: BM=128 BN=128 BK=64, 4 warps 64x64, 2 CTAs/SM ----------------
// R12 winner + cp.async burst split across ks=0/ks=1.
constexpr int BM = 128, BN = 128, BK = 64, STAGES = 3;
constexpr int ABYTES = BM * BK * 2;               // 16 KB  (128 rows x 128B, XOR-swizzled)
constexpr int BBYTES = BN * BK * 2;               // 16 KB
constexpr int STAGE_BYTES = ABYTES + BBYTES;      // 32 KB
constexpr int GSMEM = STAGES * STAGE_BYTES;       // 96 KB -> 2 CTAs/SM

__device__ __forceinline__ uint32_t smem_u32(const void* p) {
    return (uint32_t)__cvta_generic_to_shared(p);
}

__device__ __forceinline__ void mma16816(float* c, const uint32_t* a, uint32_t b0, uint32_t b1) {
    asm volatile(
        "mma.sync.aligned.m16n8k16.row.col.f32.f16.f16.f32 "
        "{%0,%1,%2,%3}, {%4,%5,%6,%7}, {%8,%9}, {%0,%1,%2,%3};"
        : "+f"(c[0]), "+f"(c[1]), "+f"(c[2]), "+f"(c[3])
        : "r"(a[0]), "r"(a[1]), "r"(a[2]), "r"(a[3]), "r"(b0), "r"(b1));
}

__global__ void __launch_bounds__(128, 2) gemm_f16(float* __restrict__ out) {
    extern __shared__ __align__(1024) char smem[];
    const uint32_t tile0 = smem_u32(smem);

    const int tid = threadIdx.x;
    const int lane = tid & 31;
    const int wid = tid >> 5;               // 4 warps
    const int wm = (wid & 1) * 64;          // 2 x 64 = BM
    const int wn = (wid >> 1) * 64;         // 2 x 64 = BN
    const int n0 = blockIdx.x * BN;
    const int m0 = blockIdx.y * BM;

    const __half* Ag = g_qx + (size_t)m0 * KTOT;
    const __half* Bg = g_wh + (size_t)n0 * KTOT;

    // rows stored as 128B (64 halves), 8 x 16B chunks, chunk XOR-swizzled by (row & 7)
    // half=0 -> first 8 chunks (j 0..7), half=1 -> last 8 (j 8..15) + commit
    auto load_half = [&](int s, int kk, int half) {
        const uint32_t base = tile0 + s * STAGE_BYTES;
#pragma unroll
        for (int j = half * 8; j < half * 8 + 8; j++) {
            const int id = tid + j * 128;          // 0..1023 A chunks, 1024..2047 B
            const int isB = id >> 10;
            const int rid = id & 1023;
            const int r = rid >> 3;
            const int c = rid & 7;
            const uint32_t dst = base + isB * ABYTES + r * 128 + (((c ^ r) & 7) << 4);
            const __half* src = (isB ? Bg : Ag) + (size_t)r * KTOT + kk + c * 8;
            asm volatile("cp.async.cg.shared.global [%0], [%1], 16;" ::"r"(dst), "l"(src));
        }
        if (half == 1) asm volatile("cp.async.commit_group;" ::: "memory");
    };

    float acc[4][8][4];
#pragma unroll
    for (int a = 0; a < 4; a++)
#pragma unroll
        for (int b = 0; b < 8; b++)
#pragma unroll
            for (int c = 0; c < 4; c++) acc[a][b][c] = 0.f;

    // one ks-step (ldmatrix + 32 mma) of the current stage
    auto ks_step = [&](uint32_t Ab, uint32_t Bb, int ks) {
        uint32_t a[4][4];
#pragma unroll
        for (int mi = 0; mi < 4; mi++) {
            const int row = wm + mi * 16 + (lane & 15);
            const int chunk = ks * 2 + (lane >> 4);
            const uint32_t addr = Ab + row * 128 + (((chunk ^ row) & 7) << 4);
            asm volatile(
                "ldmatrix.sync.aligned.m8n8.x4.shared.b16 {%0,%1,%2,%3}, [%4];"
                : "=r"(a[mi][0]), "=r"(a[mi][1]), "=r"(a[mi][2]), "=r"(a[mi][3])
                : "r"(addr));
        }
        uint32_t b[4][4];
#pragma unroll
        for (int nb = 0; nb < 4; nb++) {
            const int grp = lane >> 3;
            const int row = wn + nb * 16 + (grp >> 1) * 8 + (lane & 7);
            const int chunk = ks * 2 + (grp & 1);
            const uint32_t addr = Bb + row * 128 + (((chunk ^ row) & 7) << 4);
            asm volatile(
                "ldmatrix.sync.aligned.m8n8.x4.shared.b16 {%0,%1,%2,%3}, [%4];"
                : "=r"(b[nb][0]), "=r"(b[nb][1]), "=r"(b[nb][2]), "=r"(b[nb][3])
                : "r"(addr));
        }
#pragma unroll
        for (int mi = 0; mi < 4; mi++)
#pragma unroll
            for (int ni = 0; ni < 8; ni++)
                mma16816(acc[mi][ni], a[mi], b[ni >> 1][(ni & 1) * 2],
                         b[ni >> 1][(ni & 1) * 2 + 1]);
    };

    const int NIT = KTOT / BK;  // 64
    load_half(0, 0, 0); load_half(0, 0, 1);
    load_half(1, BK, 0); load_half(1, BK, 1);
    asm volatile("cp.async.wait_group 1;" ::: "memory");
    __syncthreads();

    for (int kt = 0; kt < NIT; kt++) {
        const int s = kt % STAGES;
        const uint32_t Ab = tile0 + s * STAGE_BYTES;
        const uint32_t Bb = Ab + ABYTES;
        const bool more = (kt + 2 < NIT);
        const int ls = (kt + 2) % STAGES;
        const int lkk = (kt + 2) * BK;

        // post-barrier: tensor work first; spread the load burst over ks=0/ks=1
        ks_step(Ab, Bb, 0);
        if (more) load_half(ls, lkk, 0);
        ks_step(Ab, Bb, 1);
        if (more) load_half(ls, lkk, 1);
        else asm volatile("cp.async.commit_group;" ::: "memory");
        ks_step(Ab, Bb, 2);
        ks_step(Ab, Bb, 3);

        asm volatile("cp.async.wait_group 1;" ::: "memory");
        __syncthreads();
    }

    // epilogue: scale by per-token x_scale, write fp32
#pragma unroll
    for (int mi = 0; mi < 4; mi++) {
        const int r0 = m0 + wm + mi * 16 + (lane >> 2);
        const float s0 = g_xs[r0];
        const float s1 = g_xs[r0 + 8];
#pragma unroll
        for (int ni = 0; ni < 8; ni++) {
            const int cc = n0 + wn + ni * 8 + (lane & 3) * 2;
            float2 v0 = make_float2(acc[mi][ni][0] * s0, acc[mi][ni][1] * s0);
            float2 v1 = make_float2(acc[mi][ni][2] * s1, acc[mi][ni][3] * s1);
            *reinterpret_cast<float2*>(out + (size_t)r0 * NT + cc) = v0;
            *reinterpret_cast<float2*>(out + (size_t)(r0 + 8) * NT + cc) = v1;
        }
    }
}

// ---------------- launch ----------------
extern "C" void kernel_launch(void* const* d_in, const int* in_sizes, int n_in,
                              void* d_out, int out_size) {
    const float* x = (const float*)d_in[0];
    const int* qw = (const int*)d_in[1];
    const int* zr = (const int*)d_in[2];
    const int* qs = (const int*)d_in[3];
    const float* bs = (const float*)d_in[4];
    const float* ss = (const float*)d_in[5];
    float* out = (float*)d_out;

    cudaFuncSetAttribute(gemm_f16, cudaFuncAttributeMaxDynamicSharedMemorySize, GSMEM);

    prep_kernel<<<MT + (NT * 512) / 256, 256>>>(x, qw, zr, qs, bs, ss);
    gemm_f16<<<dim3(NT / BN, MT / BM), 128, GSMEM>>>(out);
}